// round 15
// baseline (speedup 1.0000x reference)
#include <cuda_runtime.h>
#include <cuda_fp16.h>
#include <cstdint>

// NAIS scoring via warp-level fp16 mma.sync m16n8k16, 512-thread CTAs,
// single-iteration CTAs with A-loads hoisted above the prologue.
//
//   qp[d]  = bias[h,d] + sum_e Q[b,h,e] * Wc[h,e,d]            (fp32, exact)
//   out[k] = sum_d relu( qp[d] + (K[k,:] @ Wk)[d] ) * Wo[h,d]
//
// m16n8k16 fragments (g = lane>>2, c = lane&3), reg = f16x2 (low = 1st elem):
//   A: a0={(g,2c),(g,2c+1)} a1={(g+8,2c),..} a2={(g,2c+8),(g,2c+9)} a3={(g+8,..)}
//   B: b0={(k 2c,n=g),(k 2c+1,n=g)} b1={(k 2c+8,n=g),(k 2c+9,n=g)}
//   C: c0=(g,2c) c1=(g,2c+1) c2=(g+8,2c) c3=(g+8,2c+1)
// Column permutation (same bijection on A and B), k-tile j:
//   logical (2c,2c+1) -> cols 16j+4c,+1 ; logical (2c+8,2c+9) -> 16j+4c+2,+3
// => thread's j-th float4 (line-dense, row bytes [64j+16c,+16)) packs to
//    a0/a1 = h2(x,y), a2/a3 = h2(z,w).  Arithmetic identical to R13.
//
// R15 deltas vs R13 (100.8us, DRAM 67.4%, issue 30.2%):
//   1) KCHUNK 512, grid 4096, ONE 512-row iteration per CTA. Each warp's 8
//      LDG.128 (raw uint4, 32 regs) issue BEFORE the Bp/qp prologue; the
//      prologue + 2 syncthreads cover the DRAM latency, so the mainloop's
//      first consumer (h2 pack) finds data resident. R13 exposed one full
//      DRAM latency per iteration x 2; R15 exposes ~none.
//   2) R14's bulk L2 prefetch removed (it contended with demand loads:
//      DRAM 67->58%).

namespace {
constexpr int Bc = 32, Hc = 8, KL = 8192, Dd = 64;
constexpr int NTHREADS = 512;                 // 16 warps
constexpr int KCHUNK   = 512;                 // rows per block (one iter)
}

__device__ __forceinline__ uint32_t h2(float lo, float hi) {
    __half2 v = __floats2half2_rn(lo, hi);    // .x = lo (low 16 bits)
    return *reinterpret_cast<uint32_t*>(&v);
}

__device__ __forceinline__ uint32_t h2u(uint32_t lo, uint32_t hi) {
    return h2(__uint_as_float(lo), __uint_as_float(hi));
}

__device__ __forceinline__ void mma_f16(float c[4],
                                        uint32_t a0, uint32_t a1, uint32_t a2, uint32_t a3,
                                        uint32_t b0, uint32_t b1) {
    asm volatile(
        "mma.sync.aligned.m16n8k16.row.col.f32.f16.f16.f32 "
        "{%0,%1,%2,%3}, {%4,%5,%6,%7}, {%8,%9}, {%0,%1,%2,%3};"
        : "+f"(c[0]), "+f"(c[1]), "+f"(c[2]), "+f"(c[3])
        : "r"(a0), "r"(a1), "r"(a2), "r"(a3), "r"(b0), "r"(b1));
}

__global__ void __launch_bounds__(NTHREADS, 2)
nais_h1_kernel(const float* __restrict__ Q, const float* __restrict__ K,
               const float* __restrict__ Wc, const float* __restrict__ Wo,
               const float* __restrict__ bias, float* __restrict__ out)
{
    // Bp4h[(nt*2 + jp)*32 + lane]: k-tiles j=2jp (.x,.y) and j=2jp+1 (.z,.w)
    __shared__ uint4  Bp4h[8 * 2 * 32];       // 8 KB
    __shared__ float  qps[Dd], wos[Dd];
    __shared__ float2 qp2[32], wo2[32];       // [nt*4 + c]

    const int tid  = threadIdx.x;
    const int w    = tid >> 5;
    const int lane = tid & 31;
    const int c    = lane & 3;                // threadID_in_group
    const int g    = lane >> 2;               // groupID

    const int bid   = blockIdx.x;
    const int bh    = bid >> 4;               // b*H + h
    const int chunk = bid & 15;
    const int h     = bh & (Hc - 1);

    const float* __restrict__ WcH = Wc + (size_t)h * 2 * Dd * Dd;
    const float* __restrict__ Wk  = WcH + Dd * Dd;    // bottom half: [e][d]
    const float* __restrict__ Kc  = K + (size_t)bh * KL * Dd + (size_t)chunk * KCHUNK * Dd;
    float* __restrict__ outp = out + (size_t)bh * KL + (size_t)chunk * KCHUNK;

    // ---- A loads FIRST (raw bits, 8 x LDG.128 = 32 regs); prologue covers latency ----
    uint4 raw[2][2][4];                        // [rt][hf][j]
    {
        const int rowbase = w * 32;
        #pragma unroll
        for (int rt = 0; rt < 2; rt++)
            #pragma unroll
            for (int hf = 0; hf < 2; hf++) {
                const int r = rowbase + rt * 16 + hf * 8 + g;
                const uint4* p = reinterpret_cast<const uint4*>(Kc + (size_t)r * Dd);
                #pragma unroll
                for (int j = 0; j < 4; j++)
                    raw[rt][hf][j] = __ldcs(p + 4 * j + c);
            }
    }

    // ---- prologue (overlaps A-load latency) ----
    {   // one Bp4h entry per thread (512 entries)
        int ln = tid & 31, jp = (tid >> 5) & 1, nt = tid >> 6;
        int cc = ln & 3, gg = ln >> 2;
        int n  = nt * 8 + gg;
        int e0 = 16 * (2 * jp) + 4 * cc;
        int e1 = 16 * (2 * jp + 1) + 4 * cc;
        Bp4h[tid] = make_uint4(
            h2(Wk[(e0 + 0) * Dd + n], Wk[(e0 + 1) * Dd + n]),
            h2(Wk[(e0 + 2) * Dd + n], Wk[(e0 + 3) * Dd + n]),
            h2(Wk[(e1 + 0) * Dd + n], Wk[(e1 + 1) * Dd + n]),
            h2(Wk[(e1 + 2) * Dd + n], Wk[(e1 + 3) * Dd + n]));
    }
    if (tid < Dd) {                            // qp = bias + Q @ Wq (fp32 exact); wo
        wos[tid] = Wo[h * Dd + tid];
        float acc = bias[h * Dd + tid];
        const float* __restrict__ q = Q + (size_t)bh * Dd;
        #pragma unroll 8
        for (int e = 0; e < Dd; e++) acc = fmaf(q[e], WcH[e * Dd + tid], acc);
        qps[tid] = acc;
    }
    __syncthreads();
    if (tid < 64) {                            // pair for LDS.64 epilogue reads
        int i = tid & 31, nt = i >> 2, cc = i & 3;
        if (tid < 32) qp2[i] = make_float2(qps[nt * 8 + 2 * cc], qps[nt * 8 + 2 * cc + 1]);
        else          wo2[i] = make_float2(wos[nt * 8 + 2 * cc], wos[nt * 8 + 2 * cc + 1]);
    }
    __syncthreads();

    // ---- pack A to fp16 (raw regs die here) ----
    uint32_t A[2][2][4][2];
    #pragma unroll
    for (int rt = 0; rt < 2; rt++)
        #pragma unroll
        for (int hf = 0; hf < 2; hf++)
            #pragma unroll
            for (int j = 0; j < 4; j++) {
                A[rt][hf][j][0] = h2u(raw[rt][hf][j].x, raw[rt][hf][j].y);
                A[rt][hf][j][1] = h2u(raw[rt][hf][j].z, raw[rt][hf][j].w);
            }

    // ---- 64 mma + fused epilogue ----
    float psum[2][2] = {{0.f, 0.f}, {0.f, 0.f}};

    #pragma unroll
    for (int nt = 0; nt < 8; nt++) {
        const float2 qp = qp2[nt * 4 + c];
        const float2 wo = wo2[nt * 4 + c];

        float acc0[4] = {0.f, 0.f, 0.f, 0.f};
        float acc1[4] = {0.f, 0.f, 0.f, 0.f};

        #pragma unroll
        for (int jp = 0; jp < 2; jp++) {
            const uint4 bb = Bp4h[(nt * 2 + jp) * 32 + lane];
            const int j0 = 2 * jp, j1 = 2 * jp + 1;
            mma_f16(acc0, A[0][0][j0][0], A[0][1][j0][0],
                          A[0][0][j0][1], A[0][1][j0][1], bb.x, bb.y);
            mma_f16(acc1, A[1][0][j0][0], A[1][1][j0][0],
                          A[1][0][j0][1], A[1][1][j0][1], bb.x, bb.y);
            mma_f16(acc0, A[0][0][j1][0], A[0][1][j1][0],
                          A[0][0][j1][1], A[0][1][j1][1], bb.z, bb.w);
            mma_f16(acc1, A[1][0][j1][0], A[1][1][j1][0],
                          A[1][0][j1][1], A[1][1][j1][1], bb.z, bb.w);
        }
        psum[0][0] += fmaxf(acc0[0] + qp.x, 0.f) * wo.x + fmaxf(acc0[1] + qp.y, 0.f) * wo.y;
        psum[0][1] += fmaxf(acc0[2] + qp.x, 0.f) * wo.x + fmaxf(acc0[3] + qp.y, 0.f) * wo.y;
        psum[1][0] += fmaxf(acc1[0] + qp.x, 0.f) * wo.x + fmaxf(acc1[1] + qp.y, 0.f) * wo.y;
        psum[1][1] += fmaxf(acc1[2] + qp.x, 0.f) * wo.x + fmaxf(acc1[3] + qp.y, 0.f) * wo.y;
    }

    // reduce over the 4 lanes of each group (c = 0..3), then store
    #pragma unroll
    for (int rt = 0; rt < 2; rt++)
        #pragma unroll
        for (int hf = 0; hf < 2; hf++) {
            float p = psum[rt][hf];
            p += __shfl_xor_sync(0xffffffffu, p, 1);
            p += __shfl_xor_sync(0xffffffffu, p, 2);
            if (c == 0)
                outp[w * 32 + rt * 16 + hf * 8 + g] = p;
        }
}

extern "C" void kernel_launch(void* const* d_in, const int* in_sizes, int n_in,
                              void* d_out, int out_size)
{
    const float* Q    = (const float*)d_in[0];
    const float* K    = (const float*)d_in[1];
    const float* Wc   = (const float*)d_in[2];
    const float* Wo   = (const float*)d_in[3];
    const float* bias = (const float*)d_in[4];
    float* out = (float*)d_out;

    const int grid = Bc * Hc * (KL / KCHUNK);   // 4096 blocks
    nais_h1_kernel<<<grid, NTHREADS>>>(Q, K, Wc, Wo, bias, out);
}

// round 16
// speedup vs baseline: 1.6732x; 1.6732x over previous
#include <cuda_runtime.h>
#include <cuda_fp16.h>
#include <cstdint>

// NAIS scoring via warp-level fp16 mma.sync m16n8k16 (R13 mainloop) with the
// per-(b,h) prologue hoisted into a prep kernel.
//
//   qp[d]  = bias[h,d] + sum_e Q[b,h,e] * Wc[h,e,d]            (fp32)
//   out[k] = sum_d relu( qp[d] + (K[k,:] @ Wk)[d] ) * Wo[h,d]
//
// m16n8k16 fragments (g = lane>>2, c = lane&3), reg = f16x2 (low = 1st elem):
//   A: a0={(g,2c),(g,2c+1)} a1={(g+8,2c),..} a2={(g,2c+8),(g,2c+9)} a3={(g+8,..)}
//   B: b0={(k 2c,n=g),(k 2c+1,n=g)} b1={(k 2c+8,n=g),(k 2c+9,n=g)}
//   C: c0=(g,2c) c1=(g,2c+1) c2=(g+8,2c) c3=(g+8,2c+1)
// Column permutation (same bijection on A and B), k-tile j:
//   logical (2c,2c+1) -> cols 16j+4c,+1 ; logical (2c+8,2c+9) -> 16j+4c+2,+3
//
// R16 delta vs R13 (100.8us, DRAM 67.4%):
//   The R13 prologue (Bp pack: 16 scattered Wk LDGs/thread; qp: SERIAL 64-FMA
//   chain run by 2 of 16 warps while the rest sit at syncthreads) costs ~2.2k
//   cyc critical path PER CTA = ~15% of kernel time at grid 2048 — and the
//   values depend only on (b,h): 2048 CTAs recompute 256 unique results.
//   R16 computes them ONCE in a tiny prep kernel (grid 256, parallel-reduced
//   qp) into __device__ scratch; the main CTA prologue becomes one LDG.128 +
//   STS + 2 LDG.64 + one syncthreads (~300 cyc). Mainloop unchanged.
//   (R15's regression: grid 4096 doubled the prologue tax + raw-reg spill.)

namespace {
constexpr int Bc = 32, Hc = 8, KL = 8192, Dd = 64;
constexpr int NTHREADS = 512;                 // 16 warps
constexpr int KCHUNK   = 1024;                // rows per block
constexpr int ROWS_PER_ITER = 512;            // 16 warps x 32 rows
constexpr int NITER    = KCHUNK / ROWS_PER_ITER;  // 2
}

// per-(h) packed B fragments, per-(b,h) qp pairs, per-(h) wo pairs
__device__ uint4  g_Bp[Hc][512];              // 64 KB
__device__ float2 g_qp2[Bc * Hc][32];         // 64 KB
__device__ float2 g_wo2[Hc][32];              // 2 KB

__device__ __forceinline__ uint32_t h2(float lo, float hi) {
    __half2 v = __floats2half2_rn(lo, hi);    // .x = lo (low 16 bits)
    return *reinterpret_cast<uint32_t*>(&v);
}

__device__ __forceinline__ void mma_f16(float c[4],
                                        uint32_t a0, uint32_t a1, uint32_t a2, uint32_t a3,
                                        uint32_t b0, uint32_t b1) {
    asm volatile(
        "mma.sync.aligned.m16n8k16.row.col.f32.f16.f16.f32 "
        "{%0,%1,%2,%3}, {%4,%5,%6,%7}, {%8,%9}, {%0,%1,%2,%3};"
        : "+f"(c[0]), "+f"(c[1]), "+f"(c[2]), "+f"(c[3])
        : "r"(a0), "r"(a1), "r"(a2), "r"(a3), "r"(b0), "r"(b1));
}

// ---- prep: one block per (b,h); blocks with b==0 also pack Bp and wo2 ----
__global__ void __launch_bounds__(512)
nais_prep(const float* __restrict__ Q, const float* __restrict__ Wc,
          const float* __restrict__ Wo, const float* __restrict__ bias)
{
    __shared__ float red[512];
    __shared__ float qps_s[Dd];

    const int tid = threadIdx.x;
    const int bh  = blockIdx.x;               // 0..255
    const int h   = bh & (Hc - 1);
    const int b   = bh >> 3;

    const float* __restrict__ WcH = Wc + (size_t)h * 2 * Dd * Dd;
    const float* __restrict__ Wk  = WcH + Dd * Dd;
    const float* __restrict__ q   = Q + (size_t)bh * Dd;

    // qp = bias + Q @ Wq, parallel over (e-block i, d)
    {
        const int i = tid >> 6;               // 0..7 -> e in [8i, 8i+8)
        const int d = tid & 63;
        float partial = 0.f;
        #pragma unroll
        for (int e2 = 0; e2 < 8; e2++) {
            int e = i * 8 + e2;
            partial = fmaf(q[e], WcH[e * Dd + d], partial);
        }
        red[tid] = partial;
    }
    __syncthreads();
    if (tid < Dd) {
        float acc = bias[h * Dd + tid];
        #pragma unroll
        for (int i = 0; i < 8; i++) acc += red[i * 64 + tid];
        qps_s[tid] = acc;
    }
    __syncthreads();
    if (tid < 32) {
        int nt = tid >> 2, cc = tid & 3;
        g_qp2[bh][tid] = make_float2(qps_s[nt * 8 + 2 * cc], qps_s[nt * 8 + 2 * cc + 1]);
    }

    if (b == 0) {
        // Bp4h[(nt*2 + jp)*32 + lane]: k-tiles j=2jp (.x,.y) and j=2jp+1 (.z,.w)
        int ln = tid & 31, jp = (tid >> 5) & 1, nt = tid >> 6;
        int cc = ln & 3, gg = ln >> 2;
        int n  = nt * 8 + gg;
        int e0 = 16 * (2 * jp) + 4 * cc;
        int e1 = 16 * (2 * jp + 1) + 4 * cc;
        g_Bp[h][tid] = make_uint4(
            h2(Wk[(e0 + 0) * Dd + n], Wk[(e0 + 1) * Dd + n]),
            h2(Wk[(e0 + 2) * Dd + n], Wk[(e0 + 3) * Dd + n]),
            h2(Wk[(e1 + 0) * Dd + n], Wk[(e1 + 1) * Dd + n]),
            h2(Wk[(e1 + 2) * Dd + n], Wk[(e1 + 3) * Dd + n]));
        if (tid < 32) {
            int nt2 = tid >> 2, cc2 = tid & 3;
            g_wo2[h][tid] = make_float2(Wo[h * Dd + nt2 * 8 + 2 * cc2],
                                        Wo[h * Dd + nt2 * 8 + 2 * cc2 + 1]);
        }
    }
}

// ---- main: R13 mainloop, featherweight prologue ----
__global__ void __launch_bounds__(NTHREADS, 2)
nais_main(const float* __restrict__ K, float* __restrict__ out)
{
    __shared__ uint4  Bp4h[8 * 2 * 32];       // 8 KB
    __shared__ float2 qp2[32], wo2[32];       // [nt*4 + c]

    const int tid  = threadIdx.x;
    const int w    = tid >> 5;
    const int lane = tid & 31;
    const int c    = lane & 3;                // threadID_in_group
    const int g    = lane >> 2;               // groupID

    const int bid   = blockIdx.x;
    const int bh    = bid >> 3;               // b*H + h
    const int chunk = bid & 7;
    const int h     = bh & (Hc - 1);

    const float* __restrict__ Kc = K + (size_t)bh * KL * Dd + (size_t)chunk * KCHUNK * Dd;
    float* __restrict__ outp = out + (size_t)bh * KL + (size_t)chunk * KCHUNK;

    // prologue: one LDG.128 + STS per thread, 2 LDG.64 for 32 threads
    Bp4h[tid] = g_Bp[h][tid];
    if (tid < 32) { qp2[tid] = g_qp2[bh][tid]; wo2[tid] = g_wo2[h][tid]; }
    __syncthreads();

    // ---- main loop: 32 rows per warp per iter, A from GMEM (streaming), fp16-packed ----
    for (int it = 0; it < NITER; it++) {
        const int rowbase = it * ROWS_PER_ITER + w * 32;

        // A[rt][hf][j][0] = pack(cols 16j+4c,+1), [1] = pack(cols 16j+4c+2,+3)
        uint32_t A[2][2][4][2];
        #pragma unroll
        for (int rt = 0; rt < 2; rt++)
            #pragma unroll
            for (int hf = 0; hf < 2; hf++) {
                const int r = rowbase + rt * 16 + hf * 8 + g;
                const float4* p = reinterpret_cast<const float4*>(Kc + (size_t)r * Dd);
                #pragma unroll
                for (int j = 0; j < 4; j++) {
                    float4 f = __ldcs(p + 4 * j + c);
                    A[rt][hf][j][0] = h2(f.x, f.y);
                    A[rt][hf][j][1] = h2(f.z, f.w);
                }
            }

        float psum[2][2] = {{0.f, 0.f}, {0.f, 0.f}};

        #pragma unroll
        for (int nt = 0; nt < 8; nt++) {
            const float2 qp = qp2[nt * 4 + c];
            const float2 wo = wo2[nt * 4 + c];

            float acc0[4] = {0.f, 0.f, 0.f, 0.f};
            float acc1[4] = {0.f, 0.f, 0.f, 0.f};

            #pragma unroll
            for (int jp = 0; jp < 2; jp++) {
                const uint4 bb = Bp4h[(nt * 2 + jp) * 32 + lane];
                const int j0 = 2 * jp, j1 = 2 * jp + 1;
                mma_f16(acc0, A[0][0][j0][0], A[0][1][j0][0],
                              A[0][0][j0][1], A[0][1][j0][1], bb.x, bb.y);
                mma_f16(acc1, A[1][0][j0][0], A[1][1][j0][0],
                              A[1][0][j0][1], A[1][1][j0][1], bb.x, bb.y);
                mma_f16(acc0, A[0][0][j1][0], A[0][1][j1][0],
                              A[0][0][j1][1], A[0][1][j1][1], bb.z, bb.w);
                mma_f16(acc1, A[1][0][j1][0], A[1][1][j1][0],
                              A[1][0][j1][1], A[1][1][j1][1], bb.z, bb.w);
            }
            psum[0][0] += fmaxf(acc0[0] + qp.x, 0.f) * wo.x + fmaxf(acc0[1] + qp.y, 0.f) * wo.y;
            psum[0][1] += fmaxf(acc0[2] + qp.x, 0.f) * wo.x + fmaxf(acc0[3] + qp.y, 0.f) * wo.y;
            psum[1][0] += fmaxf(acc1[0] + qp.x, 0.f) * wo.x + fmaxf(acc1[1] + qp.y, 0.f) * wo.y;
            psum[1][1] += fmaxf(acc1[2] + qp.x, 0.f) * wo.x + fmaxf(acc1[3] + qp.y, 0.f) * wo.y;
        }

        // reduce over the 4 lanes of each group (c = 0..3), then store
        #pragma unroll
        for (int rt = 0; rt < 2; rt++)
            #pragma unroll
            for (int hf = 0; hf < 2; hf++) {
                float p = psum[rt][hf];
                p += __shfl_xor_sync(0xffffffffu, p, 1);
                p += __shfl_xor_sync(0xffffffffu, p, 2);
                if (c == 0)
                    outp[rowbase + rt * 16 + hf * 8 + g] = p;
            }
    }
}

extern "C" void kernel_launch(void* const* d_in, const int* in_sizes, int n_in,
                              void* d_out, int out_size)
{
    const float* Q    = (const float*)d_in[0];
    const float* K    = (const float*)d_in[1];
    const float* Wc   = (const float*)d_in[2];
    const float* Wo   = (const float*)d_in[3];
    const float* bias = (const float*)d_in[4];
    float* out = (float*)d_out;

    nais_prep<<<Bc * Hc, 512>>>(Q, Wc, Wo, bias);           // 256 blocks, ~3 us
    const int grid = Bc * Hc * (KL / KCHUNK);               // 2048 blocks
    nais_main<<<grid, NTHREADS>>>(K, out);
}